// round 8
// baseline (speedup 1.0000x reference)
#include <cuda_runtime.h>
#include <cuda_bf16.h>
#include <cmath>

// Fractional LIF SNN — frozen numeric contract (validated R5-R7, rel_err 2e-6):
//   * w_sh via f32 powf (libdevice __nv_powf, matches XLA-GPU)
//   * I_h: per-output single f32 accumulator, fmaf chain, k strictly ascending
//     (fma.rn.f32x2: each 64-bit lane is exactly that chain)
//   * mem sums: ascending-s f32 fmaf chains (hidden AND output)
//   * I_o: exact sum of selected f32 weights (spk in {0,1}), rounded once
//   * elementwise recurrence ops in reference f32 order
// R8 structure: GEMM (frozen) + hidden-recurrence kernel (128 blocks, no
// barriers, ballot spike masks to global) + output kernel (int64 fixed-point
// exact dots + 10-thread output recurrence).

#define B_DIM   64
#define T_DIM   64
#define NIN     784
#define NHID    512
#define NOUT    10

__device__ float    g_I[B_DIM * T_DIM * NHID];    // 8 MB hidden currents
__device__ unsigned g_spk[B_DIM * T_DIM * 16];    // 256 KB spike bitmasks

// ---------------------------------------------------------------------------
// packed f32x2 helpers
// ---------------------------------------------------------------------------
__device__ __forceinline__ unsigned long long ffma2(unsigned long long a,
                                                    unsigned long long b,
                                                    unsigned long long c) {
    unsigned long long d;
    asm("fma.rn.f32x2 %0, %1, %2, %3;" : "=l"(d) : "l"(a), "l"(b), "l"(c));
    return d;
}
__device__ __forceinline__ unsigned long long pack2(float x) {
    unsigned long long d;
    asm("mov.b64 %0, {%1, %1};" : "=l"(d) : "f"(x));
    return d;
}

// ---------------------------------------------------------------------------
// GEMM: C[m, n] = seqchain_k( A[m,k]*W[n,k] ) + bias[n]   (frozen from R6/R7)
// M = 4096, K = 784, N = 512.  128x128x16 double-buffered, 256 threads,
// 8x8 per thread as 4 packed f32x2. Bit-identical to scalar ascending chain.
// ---------------------------------------------------------------------------
#define BM 128
#define BN 128
#define BK 16
#define PAD 4

__global__ void __launch_bounds__(256, 1)
snn_gemm(const float* __restrict__ A, const float* __restrict__ W,
         const float* __restrict__ bias, float* __restrict__ C) {
    __shared__ float As[2][BK][BM + PAD];
    __shared__ float Ws[2][BK][BN + PAD];

    const int tid = threadIdx.x;
    const int tx  = tid & 15;
    const int ty  = tid >> 4;
    const int m_blk = blockIdx.x * BM;
    const int n_blk = blockIdx.y * BN;

    const int row = tid >> 2;
    const int kq4 = (tid & 3) * 4;

    const float* Ap = A + (size_t)(m_blk + row) * NIN + kq4;
    const float* Wp = W + (size_t)(n_blk + row) * NIN + kq4;

    float4 ra0, ra1, rw0, rw1;

    ra0 = *(const float4*)(Ap);
    ra1 = *(const float4*)(Ap + 64 * NIN);
    rw0 = *(const float4*)(Wp);
    rw1 = *(const float4*)(Wp + 64 * NIN);
    As[0][kq4 + 0][row] = ra0.x; As[0][kq4 + 1][row] = ra0.y;
    As[0][kq4 + 2][row] = ra0.z; As[0][kq4 + 3][row] = ra0.w;
    As[0][kq4 + 0][row + 64] = ra1.x; As[0][kq4 + 1][row + 64] = ra1.y;
    As[0][kq4 + 2][row + 64] = ra1.z; As[0][kq4 + 3][row + 64] = ra1.w;
    Ws[0][kq4 + 0][row] = rw0.x; Ws[0][kq4 + 1][row] = rw0.y;
    Ws[0][kq4 + 2][row] = rw0.z; Ws[0][kq4 + 3][row] = rw0.w;
    Ws[0][kq4 + 0][row + 64] = rw1.x; Ws[0][kq4 + 1][row + 64] = rw1.y;
    Ws[0][kq4 + 2][row + 64] = rw1.z; Ws[0][kq4 + 3][row + 64] = rw1.w;
    __syncthreads();

    unsigned long long acc[8][4];
#pragma unroll
    for (int m = 0; m < 8; m++)
#pragma unroll
        for (int j = 0; j < 4; j++) acc[m][j] = 0ULL;

    const int NKT = NIN / BK;   // 49
    for (int kt = 0; kt < NKT; kt++) {
        const int cur = kt & 1;
        if (kt < NKT - 1) {
            const float* Ap2 = Ap + (kt + 1) * BK;
            const float* Wp2 = Wp + (kt + 1) * BK;
            ra0 = *(const float4*)(Ap2);
            ra1 = *(const float4*)(Ap2 + 64 * NIN);
            rw0 = *(const float4*)(Wp2);
            rw1 = *(const float4*)(Wp2 + 64 * NIN);
        }
#pragma unroll
        for (int k = 0; k < BK; k++) {
            const float4 a01 = *(const float4*)&As[cur][k][ty * 8];
            const float4 a23 = *(const float4*)&As[cur][k][ty * 8 + 4];
            unsigned long long b2[4];
#pragma unroll
            for (int j = 0; j < 4; j++)
                b2[j] = *(const unsigned long long*)&Ws[cur][k][2 * tx + 32 * j];
            const float av[8] = {a01.x, a01.y, a01.z, a01.w,
                                 a23.x, a23.y, a23.z, a23.w};
#pragma unroll
            for (int m = 0; m < 8; m++) {
                const unsigned long long a2 = pack2(av[m]);
#pragma unroll
                for (int j = 0; j < 4; j++)
                    acc[m][j] = ffma2(a2, b2[j], acc[m][j]);
            }
        }
        if (kt < NKT - 1) {
            const int nxt = cur ^ 1;
            As[nxt][kq4 + 0][row] = ra0.x; As[nxt][kq4 + 1][row] = ra0.y;
            As[nxt][kq4 + 2][row] = ra0.z; As[nxt][kq4 + 3][row] = ra0.w;
            As[nxt][kq4 + 0][row + 64] = ra1.x; As[nxt][kq4 + 1][row + 64] = ra1.y;
            As[nxt][kq4 + 2][row + 64] = ra1.z; As[nxt][kq4 + 3][row + 64] = ra1.w;
            Ws[nxt][kq4 + 0][row] = rw0.x; Ws[nxt][kq4 + 1][row] = rw0.y;
            Ws[nxt][kq4 + 2][row] = rw0.z; Ws[nxt][kq4 + 3][row] = rw0.w;
            Ws[nxt][kq4 + 0][row + 64] = rw1.x; Ws[nxt][kq4 + 1][row + 64] = rw1.y;
            Ws[nxt][kq4 + 2][row + 64] = rw1.z; Ws[nxt][kq4 + 3][row + 64] = rw1.w;
            __syncthreads();
        }
    }

#pragma unroll
    for (int m = 0; m < 8; m++) {
        const int gm = m_blk + ty * 8 + m;
#pragma unroll
        for (int j = 0; j < 4; j++) {
            const int col = n_blk + 2 * tx + 32 * j;
            const unsigned long long v = acc[m][j];
            const float lo = __uint_as_float((unsigned)(v & 0xffffffffu));
            const float hi = __uint_as_float((unsigned)(v >> 32));
            float2 o;
            o.x = __fadd_rn(lo, bias[col]);
            o.y = __fadd_rn(hi, bias[col + 1]);
            *(float2*)&C[(size_t)gm * NHID + col] = o;
        }
    }
}

// ---------------------------------------------------------------------------
// Hidden recurrence: 128 blocks (2 per batch item) x 256 threads, no barriers
// in the time loop. Spikes exported as ballot bitmasks to g_spk.
// Numeric path identical to R7 phase 1 -> bit-identical spikes.
// ---------------------------------------------------------------------------
__global__ void __launch_bounds__(256, 1)
snn_hidden(float scale) {
    const int b    = blockIdx.x >> 1;
    const int half = blockIdx.x & 1;
    const int tid  = threadIdx.x;
    const int lane = tid & 31;
    const int wid  = tid >> 5;
    const int h    = half * 256 + tid;

    __shared__ float w_sh[T_DIM];
    if (tid < T_DIM) {
        // f32 powf == libdevice __nv_powf == XLA-GPU lowering (verified exact)
        const float lagf = (float)tid;
        w_sh[tid] = (tid >= 2)
                        ? (powf(lagf, 0.8f) - powf(lagf - 1.0f, 0.8f))
                        : 0.0f;
    }
    __syncthreads();

    float D[T_DIM];
    float V = 0.0f;   // VRESET
    const float* Ibase = g_I + (size_t)(b * T_DIM) * NHID + h;
    float Ibuf[4];
    Ibuf[0] = Ibase[0];
    Ibuf[1] = Ibase[NHID];
    Ibuf[2] = Ibase[2 * NHID];
    Ibuf[3] = Ibase[3 * NHID];
    const float GLc = 0.025f;

#pragma unroll
    for (int t = 0; t < T_DIM; t++) {
        const float Icur = Ibuf[t & 3];
        if (t + 4 < T_DIM)
            Ibuf[t & 3] = Ibase[(size_t)(t + 4) * NHID];

        // hidden memory: f32 sequential fmaf chain, s ascending (frozen)
        float mem = 0.0f;
#pragma unroll
        for (int s = 0; s <= t - 2; s++)
            mem = fmaf(w_sh[t - s], D[s], mem);

        // Caputo L1 update, f32 ops in reference order
        const float f  = __fadd_rn(__fmul_rn(-GLc, V), Icur);
        const float g  = __fmul_rn(scale, f);
        const float h2 = __fmul_rn(g, 2.0f);
        const float Vn = __fsub_rn(__fadd_rn(V, h2), mem);
        const float Vp = (Vn > 1.0f) ? 0.0f : Vn;
        D[t] = __fsub_rn(Vp, V);
        V = Vp;

        const unsigned msk = __ballot_sync(0xffffffffu, Vn > 1.0f);
        if (lane == 0)
            g_spk[(b * T_DIM + t) * 16 + half * 8 + wid] = msk;
    }
}

// ---------------------------------------------------------------------------
// Output layer: 64 blocks (per batch item) x 512 threads.
//   phase 2: I_o[t][o] = exact sum of selected f32 W_o entries via int64
//            fixed-point (w * 2^53 is an exact integer for |w| >= 2^-30),
//            rounded once -> same f32 as the fp64-exact path.
//   phase 3: output recurrence on 10 threads (frozen f32 chains).
// ---------------------------------------------------------------------------
#define FIX  9007199254740992.0   // 2^53

__global__ void __launch_bounds__(512, 1)
snn_out(const float* __restrict__ Wo, const float* __restrict__ bo,
        float* __restrict__ out, float scale) {
    const int b    = blockIdx.x;
    const int tid  = threadIdx.x;
    const int lane = tid & 31;
    const int wid  = tid >> 5;

    __shared__ float     w_sh[T_DIM];
    __shared__ unsigned  msk_sh[T_DIM][16];       // 4 KB
    __shared__ long long Wo_i[NOUT][NHID];        // 40 KB
    __shared__ float     Io_sh[T_DIM][NOUT];      // 2.5 KB

    if (tid < T_DIM) {
        const float lagf = (float)tid;
        w_sh[tid] = (tid >= 2)
                        ? (powf(lagf, 0.8f) - powf(lagf - 1.0f, 0.8f))
                        : 0.0f;
    }
    for (int i = tid; i < T_DIM * 16; i += 512)
        msk_sh[i >> 4][i & 15] = g_spk[b * T_DIM * 16 + i];
    for (int i = tid; i < NOUT * NHID; i += 512)
        Wo_i[i / NHID][i % NHID] = (long long)((double)Wo[i] * FIX);
    __syncthreads();

    // ---- phase 2: 640 selective sums; warp w handles t = 4w .. 4w+3 -------
    {
        const unsigned bit = 1u << lane;
        const int t0 = wid * 4;
#pragma unroll
        for (int tt = 0; tt < 4; tt++) {
            const int t = t0 + tt;
            unsigned m[16];
#pragma unroll
            for (int j = 0; j < 16; j++) m[j] = msk_sh[t][j];
            for (int o = 0; o < NOUT; o++) {
                long long s = 0;
#pragma unroll
                for (int j = 0; j < 16; j++)
                    if (m[j] & bit) s += Wo_i[o][j * 32 + lane];
#pragma unroll
                for (int off = 16; off > 0; off >>= 1)
                    s += __shfl_xor_sync(0xffffffffu, s, off);
                if (lane == 0)
                    Io_sh[t][o] =
                        __fadd_rn((float)((double)s * (1.0 / FIX)), bo[o]);
            }
        }
    }
    __syncthreads();

    // ---- phase 3: output recurrence (10 threads) --------------------------
    if (tid < NOUT) {
        const int o = tid;
        float Do[T_DIM];
        float Vo = 0.0f;
        const float GLc = 0.025f;

#pragma unroll
        for (int t = 0; t < T_DIM; t++) {
            // output memory: f32 sequential fmaf chain, s ascending (frozen)
            float mo = 0.0f;
#pragma unroll
            for (int s = 0; s <= t - 2; s++)
                mo = fmaf(w_sh[t - s], Do[s], mo);

            const float Io  = Io_sh[t][o];
            const float fo  = __fadd_rn(__fmul_rn(-GLc, Vo), Io);
            const float go  = __fmul_rn(scale, fo);
            const float ho  = __fmul_rn(go, 2.0f);
            const float Von = __fsub_rn(__fadd_rn(Vo, ho), mo);
            const float spko = (Von > 1.0f) ? 1.0f : 0.0f;
            const float Vop  = (Von > 1.0f) ? 0.0f : Von;
            Do[t] = __fsub_rn(Vop, Vo);
            Vo = Vop;

            const int idx = (t * B_DIM + b) * NOUT + o;
            out[idx] = spko;                               // spk_trace [T,B,O]
            out[T_DIM * B_DIM * NOUT + idx] = Vo;          // mem_trace [T,B,O]
        }
    }
}

// ---------------------------------------------------------------------------
extern "C" void kernel_launch(void* const* d_in, const int* in_sizes, int n_in,
                              void* d_out, int out_size) {
    const float* data = (const float*)d_in[0];   // [B,T,NIN]
    const float* W_h  = (const float*)d_in[1];   // [NHID,NIN]
    const float* b_h  = (const float*)d_in[2];   // [NHID]
    const float* W_o  = (const float*)d_in[3];   // [NOUT,NHID]
    const float* b_o  = (const float*)d_in[4];   // [NOUT]
    // d_in[5] = plotting (unused)

    float* I_ptr = nullptr;
    cudaGetSymbolAddress((void**)&I_ptr, g_I);   // no alloc; capture-safe

    const float scale = (float)(pow(0.1, 0.2) * tgamma(1.8));

    dim3 ggrid(B_DIM * T_DIM / BM, NHID / BN);   // (32, 4)
    snn_gemm<<<ggrid, 256>>>(data, W_h, b_h, I_ptr);
    snn_hidden<<<2 * B_DIM, 256>>>(scale);
    snn_out<<<B_DIM, 512>>>(W_o, b_o, (float*)d_out, scale);
}